// round 12
// baseline (speedup 1.0000x reference)
#include <cuda_runtime.h>
#include <math.h>

#define NQ    12
#define DIM   4096
#define BATCH 8
#define SEQ   64
#define BT    (BATCH*SEQ)
#define NTHR  256
#define KREG  16

#define PI_D 3.14159265358979323846

typedef unsigned long long u64;

// QKV features [head*3+proj][bt][12]
__device__ float  g_qkv[6*BT*NQ];
__device__ float2 g_ryres[36];        // reservoir RY coeffs (cos(t/2), sin(t/2))
__device__ float2 g_ryproj[144];      // projection RY coeffs
__device__ float2 g_diag[12*128];     // diag tables: pass*128 + (lo:0-63 | hi:64-127)
__device__ int    g_done;             // completion counter (reset by last CTA)
__device__ u64    g_encs[(size_t)BT * DIM];   // enc snapshots (L2-resident, 16MB)

// ---------------- packed f32x2 helpers ----------------
__device__ __forceinline__ u64 pk2(float lo, float hi) {
    u64 r; asm("mov.b64 %0,{%1,%2};" : "=l"(r) : "f"(lo), "f"(hi)); return r;
}
__device__ __forceinline__ float2 up2(u64 v) {
    float2 r; asm("mov.b64 {%0,%1},%2;" : "=f"(r.x), "=f"(r.y) : "l"(v)); return r;
}
__device__ __forceinline__ u64 mul2_(u64 a, u64 b) {
    u64 d; asm("mul.rn.f32x2 %0,%1,%2;" : "=l"(d) : "l"(a), "l"(b)); return d;
}
__device__ __forceinline__ u64 fma2_(u64 a, u64 b, u64 c) {
    u64 d; asm("fma.rn.f32x2 %0,%1,%2,%3;" : "=l"(d) : "l"(a), "l"(b), "l"(c)); return d;
}
#define NEGM 0x8000000080000000ULL

// ---------------- complex helpers ----------------
__device__ __forceinline__ float2 cmul(float2 a, float2 b) {
    return make_float2(a.x*b.x - a.y*b.y, a.x*b.y + a.y*b.x);
}

// ---------------- setup: RY coeffs + diag tables (CZ folded in) ----------------
__global__ void qtf_setup(const float* __restrict__ resp, const float* __restrict__ headp)
{
    int j = blockIdx.x * blockDim.x + threadIdx.x;
    if (j < 36) {
        float t = resp[j*3];
        g_ryres[j] = make_float2(cosf(0.5f*t), sinf(0.5f*t));
    } else if (j < 180) {
        int s = j - 36, hp = s / 24, gi = s % 24;
        float t = headp[hp*48 + gi*2];
        g_ryproj[s] = make_float2(cosf(0.5f*t), sinf(0.5f*t));
    }
    int e = j - 192;
    if (e >= 0 && e < 12*128) {
        int pass = e >> 7, m = e & 127;
        int is_hi = (m >> 6) & 1, mb = m & 63;
        float ph = 0.f;
        for (int i = 0; i < 6; i++) {
            if ((mb >> i) & 1) {
                int q = i + is_hi*6;
                float f;
                if (pass < 6) {
                    int l = pass >> 1, kind = pass & 1;
                    f = resp[(l*12 + q)*3 + (kind ? 1 : 2)];
                } else {
                    f = headp[(pass - 6)*48 + q*2 + 1];
                }
                ph += f;
            }
        }
        float2 v = make_float2(cosf(ph), sinf(ph));
        int neg = 0;
        if (pass == 1 || pass == 5)       // CZ 0x555 in-half pairs
            neg = __popc(mb & (mb >> 1) & 0x15) & 1;
        else if (pass == 3)               // CZ 0x2AA in-half pairs
            neg = __popc(mb & (mb >> 1) & 0x0A) & 1;
        if (neg) { v.x = -v.x; v.y = -v.y; }
        g_diag[pass*128 + m] = v;
    }
}

// ---------------- layouts ----------------
__device__ __forceinline__ int addrA(int tid, int k) { return (k<<8) | tid; }
__device__ __forceinline__ int addrB(int tid, int k) {
    return (tid & 31) | ((k & 7) << 5) | ((tid >> 5) << 8) | ((k >> 3) << 11);
}
__device__ __forceinline__ int ladd(int d) {
    return ((d ^ (d << 1)) & 0xFFE) | (d & 1);
}

// ---------------- packed RY gate primitives ----------------
__device__ __forceinline__ void ry_lane(u64 st[KREG], int tid, int i, float2 cs)
{
    unsigned lm = 1u << i;
    float s = ((tid >> i) & 1) ? cs.y : -cs.y;
    u64 c2 = pk2(cs.x, cs.x), s2 = pk2(s, s);
    #pragma unroll
    for (int k = 0; k < KREG; k++) {
        float2 v = up2(st[k]);
        float ox = __shfl_xor_sync(0xffffffffu, v.x, lm);
        float oy = __shfl_xor_sync(0xffffffffu, v.y, lm);
        st[k] = fma2_(c2, st[k], mul2_(s2, pk2(ox, oy)));
    }
}
__device__ __forceinline__ void ry_local(u64 st[KREG], int m, float2 cs)
{
    u64 c2 = pk2(cs.x, cs.x), s2 = pk2(cs.y, cs.y), ns2 = pk2(-cs.y, -cs.y);
    #pragma unroll
    for (int k = 0; k < KREG; k++) {
        if (k & m) continue;
        int kk = k | m;
        u64 a = st[k], b = st[kk];
        st[k]  = fma2_(c2, a, mul2_(ns2, b));
        st[kk] = fma2_(s2, a, mul2_(c2, b));
    }
}

// ---------------- diagonal passes ----------------
__device__ __forceinline__ void diagA(u64 st[KREG], const float2* T, int tid)
{
    float2 L = __ldg(&T[tid & 63]);
    int tt = tid >> 6;
    #pragma unroll
    for (int k = 0; k < KREG; k++) {
        float2 u = cmul(L, __ldg(&T[64 + ((k<<2) | tt)]));
        float2 v = up2(st[k]);
        st[k] = pk2(v.x*u.x - v.y*u.y, v.x*u.y + v.y*u.x);
    }
}
__device__ __forceinline__ void diagB(u64 st[KREG], const float2* T, int tid)
{
    int lo0 = tid & 31, t57 = tid >> 5;
    #pragma unroll
    for (int k = 0; k < KREG; k++) {
        float2 L = __ldg(&T[lo0 | ((k & 1) << 5)]);
        float2 H = __ldg(&T[64 + (((k>>1) & 3) | (t57 << 2) | ((k>>3) << 5))]);
        float2 u = cmul(L, H);
        float2 v = up2(st[k]);
        st[k] = pk2(v.x*u.x - v.y*u.y, v.x*u.y + v.y*u.x);
    }
}

__device__ __forceinline__ void cx011(u64 st[KREG], int tid)
{
    if (tid & 1) {
        #pragma unroll
        for (int k = 0; k < 8; k++) {
            u64 t = st[k]; st[k] = st[k+8]; st[k+8] = t;
        }
    }
}

// ---------------- layout roundtrips ----------------
__device__ __forceinline__ void rtAB(u64 st[KREG], u64* work, int tid, bool ladder)
{
    __syncthreads();
    #pragma unroll
    for (int k = 0; k < KREG; k++) work[addrA(tid, k)] = st[k];
    __syncthreads();
    #pragma unroll
    for (int k = 0; k < KREG; k++) {
        int D = addrB(tid, k);
        st[k] = work[ladder ? ladd(D) : D];
    }
}
__device__ __forceinline__ void rtBA(u64 st[KREG], u64* work, int tid)
{
    __syncthreads();
    #pragma unroll
    for (int k = 0; k < KREG; k++) work[addrB(tid, k)] = st[k];
    __syncthreads();
    #pragma unroll
    for (int k = 0; k < KREG; k++) st[k] = work[addrA(tid, k)];
}

extern __shared__ u64 smem_u64[];
// [0,4096) work   then 180 float2 coeffs

__global__ void __launch_bounds__(NTHR, 4) qtf_main(
    const float* __restrict__ seq,
    const float* __restrict__ W1, const float* __restrict__ b1,
    const float* __restrict__ W2, const float* __restrict__ b2,
    float* __restrict__ out)
{
    u64* work   = smem_u64;
    float2* sry = (float2*)(smem_u64 + 4096);
    const int tid = threadIdx.x;
    // heavy-first remap: blocks 0..7 are the t=63 (6-projection) CTAs
    int b_, t_;
    if (blockIdx.x < 8) { b_ = blockIdx.x; t_ = SEQ - 1; }
    else { int ix = blockIdx.x - 8; b_ = ix / 63; t_ = ix % 63; }
    const int bt = b_ * SEQ + t_;
    const int t  = t_;
    const float x = seq[bt];
    u64* encg = g_encs + ((size_t)bt << 12);

    for (int j = tid; j < 36;  j += NTHR) sry[j]    = g_ryres[j];
    for (int j = tid; j < 144; j += NTHR) sry[36+j] = g_ryproj[j];

    u64 st[KREG];

    // ======== encode: product state with folded ladder+ring perm (layout A) ========
    {
        float2 F = make_float2(1.0f, 0.0f);
        float2 wv[6][2];
        #pragma unroll
        for (int i = 0; i < NQ; i++) {
            float th = x * (float)(PI_D * (double)(i + 1) / 12.0);
            float ph = x * (float)(PI_D / (double)(i + 1));
            float s, c, sh, ch;
            __sincosf(0.5f*th, &s, &c);
            __sincosf(0.5f*ph, &sh, &ch);
            float am = (c - s) * 0.70710678118654752f;
            float ap = (c + s) * 0.70710678118654752f;
            float2 v0 = make_float2(am*ch, -am*sh);
            float2 v1 = make_float2(ap*ch,  ap*sh);
            if (i >= 2 && i <= 7) {
                int bit = ((tid >> (i-1)) ^ (tid >> i)) & 1;
                F = cmul(F, bit ? v1 : v0);
            } else {
                int vi = (i < 2) ? i : (i - 6);
                wv[vi][0] = v0; wv[vi][1] = v1;
            }
        }
        int a0 = tid & 1, a1 = (tid >> 1) & 1, a7 = (tid >> 7) & 1;
        #pragma unroll
        for (int k = 0; k < KREG; k++) {
            int k0 = k & 1, k1 = (k >> 1) & 1, k2 = (k >> 2) & 1, k3 = (k >> 3) & 1;
            float2 a = cmul(F, (a0 ^ k3)      ? wv[0][1] : wv[0][0]);
            a = cmul(a, (a0 ^ a1 ^ k3) ? wv[1][1] : wv[1][0]);
            a = cmul(a, (a7 ^ k0)      ? wv[2][1] : wv[2][0]);
            a = cmul(a, (k0 ^ k1)      ? wv[3][1] : wv[3][0]);
            a = cmul(a, (k1 ^ k2)      ? wv[4][1] : wv[4][0]);
            a = cmul(a, (k2 ^ k3)      ? wv[5][1] : wv[5][0]);
            st[k] = pk2(a.x, a.y);
        }
    }
    __syncthreads();

    // ======== reservoir ========
    diagA(st, g_diag + 0*128, tid);
    #pragma unroll
    for (int i = 0; i < 5; i++) ry_lane(st, tid, i, sry[i]);
    ry_local(st, 1, sry[8]);  ry_local(st, 2, sry[9]);
    ry_local(st, 4, sry[10]); ry_local(st, 8, sry[11]);
    rtAB(st, work, tid, false);
    ry_local(st, 1, sry[5]);  ry_local(st, 2, sry[6]); ry_local(st, 4, sry[7]);
    diagB(st, g_diag + 1*128, tid);
    cx011(st, tid);

    diagB(st, g_diag + 2*128, tid);
    #pragma unroll
    for (int i = 0; i < 5; i++) ry_lane(st, tid, i, sry[12+i]);
    ry_local(st, 1, sry[12+5]); ry_local(st, 2, sry[12+6]);
    ry_local(st, 4, sry[12+7]); ry_local(st, 8, sry[12+11]);
    rtBA(st, work, tid);
    ry_local(st, 1, sry[12+8]); ry_local(st, 2, sry[12+9]); ry_local(st, 4, sry[12+10]);
    diagA(st, g_diag + 3*128, tid);
    if (((tid >> 5) & (tid >> 6)) & 1) {
        #pragma unroll
        for (int k = 0; k < KREG; k++) st[k] ^= NEGM;
    }
    cx011(st, tid);

    diagA(st, g_diag + 4*128, tid);
    #pragma unroll
    for (int i = 0; i < 5; i++) ry_lane(st, tid, i, sry[24+i]);
    ry_local(st, 1, sry[24+8]);  ry_local(st, 2, sry[24+9]);
    ry_local(st, 4, sry[24+10]); ry_local(st, 8, sry[24+11]);
    rtAB(st, work, tid, false);
    ry_local(st, 1, sry[24+5]);  ry_local(st, 2, sry[24+6]); ry_local(st, 4, sry[24+7]);
    diagB(st, g_diag + 5*128, tid);
    cx011(st, tid);

    // snapshot encoded state (layout B) to L2-resident global
    #pragma unroll
    for (int k = 0; k < KREG; k++) encg[(k<<8) | tid] = st[k];

    // ======== projections (Q only at t = SEQ-1) ========
    __shared__ float red[NQ];
    const bool lastt = (t == SEQ - 1);
    bool first = true;
    for (int h = 0; h < 2; h++) {
        for (int p = 0; p < 3; p++) {
            if (p == 0 && !lastt) continue;
            if (!first) {
                #pragma unroll
                for (int k = 0; k < KREG; k++) st[k] = __ldg(&encg[(k<<8) | tid]);
            }
            first = false;
            const int hp = h*3 + p;
            const float2* gp = sry + 36 + hp*24;
            #pragma unroll
            for (int i = 0; i < 5; i++) ry_lane(st, tid, i, gp[i]);
            ry_local(st, 1, gp[5]); ry_local(st, 2, gp[6]);
            ry_local(st, 4, gp[7]); ry_local(st, 8, gp[11]);
            rtBA(st, work, tid);
            ry_local(st, 1, gp[8]); ry_local(st, 2, gp[9]); ry_local(st, 4, gp[10]);
            diagA(st, g_diag + (6 + hp)*128, tid);
            rtAB(st, work, tid, true);
            #pragma unroll
            for (int i = 0; i < 5; i++) ry_lane(st, tid, i, gp[12+i]);
            ry_local(st, 1, gp[12+5]); ry_local(st, 2, gp[12+6]);
            ry_local(st, 4, gp[12+7]); ry_local(st, 8, gp[12+11]);
            rtBA(st, work, tid);
            ry_local(st, 1, gp[12+8]); ry_local(st, 2, gp[12+9]); ry_local(st, 4, gp[12+10]);

            float S = 0.f, B0 = 0.f, B1 = 0.f, B2 = 0.f, B3 = 0.f;
            #pragma unroll
            for (int k = 0; k < KREG; k++) {
                float2 v = up2(st[k]);
                float pr = fmaf(v.x, v.x, v.y*v.y);
                S += pr;
                B0 += ( k          & 1) ? -pr : pr;
                B1 += ((k ^ (k>>1))& 1) ? -pr : pr;
                B2 += (__popc(k & 7)  & 1) ? -pr : pr;
                B3 += (__popc(k & 15) & 1) ? -pr : pr;
            }
            float tsgn = (__popc(tid) & 1) ? -1.f : 1.f;
            float acc[NQ];
            acc[0] = tsgn * B3;
            acc[1] = tsgn * B2;
            acc[2] = tsgn * B1;
            acc[3] = tsgn * B0;
            #pragma unroll
            for (int q = 4; q < NQ; q++) {
                int mt = 0xFF >> (q - 4);
                acc[q] = (__popc(tid & mt) & 1) ? -S : S;
            }
            #pragma unroll
            for (int q = 0; q < NQ; q++) {
                float v = acc[q];
                #pragma unroll
                for (int o = 16; o; o >>= 1)
                    v += __shfl_xor_sync(0xffffffffu, v, o);
                acc[q] = v;
            }
            if (tid < NQ) red[tid] = 0.f;
            __syncthreads();
            if ((tid & 31) == 0) {
                #pragma unroll
                for (int q = 0; q < NQ; q++) atomicAdd(&red[q], acc[q]);
            }
            __syncthreads();
            if (tid < NQ)
                g_qkv[(hp*BT + bt)*NQ + tid] = red[tid];
            __syncthreads();
        }
    }

    // ======== last CTA runs attention + MLP inline ========
    __shared__ int s_last;
    __threadfence();
    if (tid == 0) s_last = (atomicAdd(&g_done, 1) == BT - 1) ? 1 : 0;
    __syncthreads();
    if (!s_last) return;
    if (tid == 0) g_done = 0;        // reset for next graph replay
    __threadfence();

    float* feat = (float*)work;      // 8 b * 24
    float* hdn  = feat + 192;        // 8 b * 48
    const int w = tid >> 5, l = tid & 31;
    for (int task = w; task < 16; task += 8) {
        int b = task >> 1, h = task & 1;
        const float* Q = &g_qkv[((h*3 + 0)*BT + b*SEQ + (SEQ-1))*NQ];
        const float* K = &g_qkv[((h*3 + 1)*BT + b*SEQ)*NQ];
        const float* V = &g_qkv[((h*3 + 2)*BT + b*SEQ)*NQ];
        float sc0 = 0.f, sc1 = 0.f;
        #pragma unroll
        for (int q = 0; q < NQ; q++) {
            float qv = Q[q];
            sc0 = fmaf(qv, K[l*NQ + q],      sc0);
            sc1 = fmaf(qv, K[(l+32)*NQ + q], sc1);
        }
        sc0 *= 0.28867513459481287f;
        sc1 *= 0.28867513459481287f;
        float m = fmaxf(sc0, sc1);
        #pragma unroll
        for (int o = 16; o; o >>= 1)
            m = fmaxf(m, __shfl_xor_sync(0xffffffffu, m, o));
        float e0 = expf(sc0 - m), e1 = expf(sc1 - m);
        float sum = e0 + e1;
        #pragma unroll
        for (int o = 16; o; o >>= 1)
            sum += __shfl_xor_sync(0xffffffffu, sum, o);
        float inv = 1.0f / sum;
        float w0 = e0 * inv, w1 = e1 * inv;
        #pragma unroll
        for (int d = 0; d < NQ; d++) {
            float v = fmaf(w0, V[l*NQ + d], w1 * V[(l+32)*NQ + d]);
            #pragma unroll
            for (int o = 16; o; o >>= 1)
                v += __shfl_xor_sync(0xffffffffu, v, o);
            if (l == 0) feat[b*24 + h*NQ + d] = v;
        }
    }
    __syncthreads();
    for (int idx = tid; idx < 384; idx += NTHR) {
        int b = idx / 48, j = idx % 48;
        float a = b1[j];
        #pragma unroll
        for (int i = 0; i < 24; i++) a = fmaf(feat[b*24 + i], W1[i*48 + j], a);
        hdn[b*48 + j] = 0.5f * a * (1.0f + erff(a * 0.7071067811865476f));
    }
    __syncthreads();
    if (tid < 32) {
        int b = tid >> 2, o = tid & 3;
        float a = b2[o];
        #pragma unroll
        for (int j = 0; j < 48; j++) a = fmaf(hdn[b*48 + j], W2[j*4 + o], a);
        out[b*4 + o] = a;
    }
}

extern "C" void kernel_launch(void* const* d_in, const int* in_sizes, int n_in,
                              void* d_out, int out_size)
{
    const float* seq   = (const float*)d_in[0];
    const float* resp  = (const float*)d_in[1];
    const float* headp = (const float*)d_in[2];
    const float* W1    = (const float*)d_in[3];
    const float* b1    = (const float*)d_in[4];
    const float* W2    = (const float*)d_in[5];
    const float* b2    = (const float*)d_in[6];
    float* out = (float*)d_out;

    size_t shbytes = 4096ull*sizeof(u64) + 180ull*sizeof(float2);   // 34,208 B -> occ 4
    cudaFuncSetAttribute(qtf_main, cudaFuncAttributeMaxDynamicSharedMemorySize, (int)shbytes);

    qtf_setup<<<8, 256>>>(resp, headp);
    qtf_main<<<BT, NTHR, shbytes>>>(seq, W1, b1, W2, b2, out);
}

// round 14
// speedup vs baseline: 1.0282x; 1.0282x over previous
#include <cuda_runtime.h>
#include <math.h>

#define NQ    12
#define DIM   4096
#define BATCH 8
#define SEQ   64
#define BT    (BATCH*SEQ)
#define NTHR  256
#define KREG  16

#define PI_D 3.14159265358979323846

typedef unsigned long long u64;

// QKV features [head*3+proj][bt][12]
__device__ float  g_qkv[6*BT*NQ];
__device__ float2 g_ryres[36];        // reservoir RY coeffs (cos(t/2), sin(t/2))
__device__ float2 g_ryproj[144];      // projection RY coeffs
__device__ float2 g_diag[12*128];     // diag tables: pass*128 + (lo:0-63 | hi:64-127)
__device__ int    g_done;             // completion counter (reset by last CTA)

// ---------------- packed f32x2 helpers ----------------
__device__ __forceinline__ u64 pk2(float lo, float hi) {
    u64 r; asm("mov.b64 %0,{%1,%2};" : "=l"(r) : "f"(lo), "f"(hi)); return r;
}
__device__ __forceinline__ float2 up2(u64 v) {
    float2 r; asm("mov.b64 {%0,%1},%2;" : "=f"(r.x), "=f"(r.y) : "l"(v)); return r;
}
__device__ __forceinline__ u64 mul2_(u64 a, u64 b) {
    u64 d; asm("mul.rn.f32x2 %0,%1,%2;" : "=l"(d) : "l"(a), "l"(b)); return d;
}
__device__ __forceinline__ u64 fma2_(u64 a, u64 b, u64 c) {
    u64 d; asm("fma.rn.f32x2 %0,%1,%2,%3;" : "=l"(d) : "l"(a), "l"(b), "l"(c)); return d;
}
#define NEGM 0x8000000080000000ULL

// ---------------- complex helpers ----------------
__device__ __forceinline__ float2 cmul(float2 a, float2 b) {
    return make_float2(a.x*b.x - a.y*b.y, a.x*b.y + a.y*b.x);
}

// ---------------- setup: RY coeffs + diag tables (CZ folded in) ----------------
__global__ void qtf_setup(const float* __restrict__ resp, const float* __restrict__ headp)
{
    int j = blockIdx.x * blockDim.x + threadIdx.x;
    if (j < 36) {
        float t = resp[j*3];
        g_ryres[j] = make_float2(cosf(0.5f*t), sinf(0.5f*t));
    } else if (j < 180) {
        int s = j - 36, hp = s / 24, gi = s % 24;
        float t = headp[hp*48 + gi*2];
        g_ryproj[s] = make_float2(cosf(0.5f*t), sinf(0.5f*t));
    }
    int e = j - 192;
    if (e >= 0 && e < 12*128) {
        int pass = e >> 7, m = e & 127;
        int is_hi = (m >> 6) & 1, mb = m & 63;
        float ph = 0.f;
        for (int i = 0; i < 6; i++) {
            if ((mb >> i) & 1) {
                int q = i + is_hi*6;
                float f;
                if (pass < 6) {
                    int l = pass >> 1, kind = pass & 1;
                    f = resp[(l*12 + q)*3 + (kind ? 1 : 2)];
                } else {
                    f = headp[(pass - 6)*48 + q*2 + 1];
                }
                ph += f;
            }
        }
        float2 v = make_float2(cosf(ph), sinf(ph));
        int neg = 0;
        if (pass == 1 || pass == 5)       // CZ 0x555 in-half pairs
            neg = __popc(mb & (mb >> 1) & 0x15) & 1;
        else if (pass == 3)               // CZ 0x2AA in-half pairs
            neg = __popc(mb & (mb >> 1) & 0x0A) & 1;
        if (neg) { v.x = -v.x; v.y = -v.y; }
        g_diag[pass*128 + m] = v;
    }
}

// ---------------- layouts ----------------
// A: locals q8-11 (k0-3);  lanes q0-4;      warps q5-7
// B: locals q5,6,7,11;     lanes q0-4;      warps q8-10
// C: locals q0-3 (k0-3);   lanes q4,5,6,7,11 -> l0-4; warps q8-10
__device__ __forceinline__ int addrA(int tid, int k) { return (k<<8) | tid; }
__device__ __forceinline__ int addrB(int tid, int k) {
    return (tid & 31) | ((k & 7) << 5) | ((tid >> 5) << 8) | ((k >> 3) << 11);
}
__device__ __forceinline__ int addrC(int tid, int k) {
    return (k & 15) | ((tid & 15) << 4) | (((tid >> 5) & 7) << 8) | (((tid >> 4) & 1) << 11);
}
__device__ __forceinline__ int ladd(int d) {      // CX-ladder gather source
    return ((d ^ (d << 1)) & 0xFFE) | (d & 1);
}
__device__ __forceinline__ int swz(int d) {       // bank-conflict swizzle for work buffer
    return d ^ ((d >> 4) & 0xF);
}

// ---------------- packed RY gate primitives ----------------
__device__ __forceinline__ void ry_lane(u64 st[KREG], int tid, int i, float2 cs)
{
    unsigned lm = 1u << i;
    float s = ((tid >> i) & 1) ? cs.y : -cs.y;
    u64 c2 = pk2(cs.x, cs.x), s2 = pk2(s, s);
    #pragma unroll
    for (int k = 0; k < KREG; k++) {
        float2 v = up2(st[k]);
        float ox = __shfl_xor_sync(0xffffffffu, v.x, lm);
        float oy = __shfl_xor_sync(0xffffffffu, v.y, lm);
        st[k] = fma2_(c2, st[k], mul2_(s2, pk2(ox, oy)));
    }
}
__device__ __forceinline__ void ry_local(u64 st[KREG], int m, float2 cs)
{
    u64 c2 = pk2(cs.x, cs.x), s2 = pk2(cs.y, cs.y), ns2 = pk2(-cs.y, -cs.y);
    #pragma unroll
    for (int k = 0; k < KREG; k++) {
        if (k & m) continue;
        int kk = k | m;
        u64 a = st[k], b = st[kk];
        st[k]  = fma2_(c2, a, mul2_(ns2, b));
        st[kk] = fma2_(s2, a, mul2_(c2, b));
    }
}

// ---------------- diagonal passes ----------------
__device__ __forceinline__ void diagA(u64 st[KREG], const float2* T, int tid)
{
    float2 L = __ldg(&T[tid & 63]);
    int tt = tid >> 6;
    #pragma unroll
    for (int k = 0; k < KREG; k++) {
        float2 u = cmul(L, __ldg(&T[64 + ((k<<2) | tt)]));
        float2 v = up2(st[k]);
        st[k] = pk2(v.x*u.x - v.y*u.y, v.x*u.y + v.y*u.x);
    }
}
__device__ __forceinline__ void diagB(u64 st[KREG], const float2* T, int tid)
{
    int lo0 = tid & 31, t57 = tid >> 5;
    #pragma unroll
    for (int k = 0; k < KREG; k++) {
        float2 L = __ldg(&T[lo0 | ((k & 1) << 5)]);
        float2 H = __ldg(&T[64 + (((k>>1) & 3) | (t57 << 2) | ((k>>3) << 5))]);
        float2 u = cmul(L, H);
        float2 v = up2(st[k]);
        st[k] = pk2(v.x*u.x - v.y*u.y, v.x*u.y + v.y*u.x);
    }
}
// layout C: d&63 = k | ((tid&3)<<4);  d>>6 = ((tid>>2)&3)|(((tid>>5)&7)<<2)|(((tid>>4)&1)<<5)
__device__ __forceinline__ void diagC(u64 st[KREG], const float2* T, int tid)
{
    int hi = ((tid >> 2) & 3) | (((tid >> 5) & 7) << 2) | (((tid >> 4) & 1) << 5);
    float2 H = __ldg(&T[64 + hi]);
    int lbase = (tid & 3) << 4;
    #pragma unroll
    for (int k = 0; k < KREG; k++) {
        float2 u = cmul(__ldg(&T[k | lbase]), H);
        float2 v = up2(st[k]);
        st[k] = pk2(v.x*u.x - v.y*u.y, v.x*u.y + v.y*u.x);
    }
}

__device__ __forceinline__ void cx011(u64 st[KREG], int tid)
{
    if (tid & 1) {
        #pragma unroll
        for (int k = 0; k < 8; k++) {
            u64 t = st[k]; st[k] = st[k+8]; st[k+8] = t;
        }
    }
}

// ---------------- layout roundtrips (swizzled work buffer) ----------------
__device__ __forceinline__ void rtAB(u64 st[KREG], u64* work, int tid)
{
    __syncthreads();
    #pragma unroll
    for (int k = 0; k < KREG; k++) work[swz(addrA(tid, k))] = st[k];
    __syncthreads();
    #pragma unroll
    for (int k = 0; k < KREG; k++) st[k] = work[swz(addrB(tid, k))];
}
__device__ __forceinline__ void rtBA(u64 st[KREG], u64* work, int tid)
{
    __syncthreads();
    #pragma unroll
    for (int k = 0; k < KREG; k++) work[swz(addrB(tid, k))] = st[k];
    __syncthreads();
    #pragma unroll
    for (int k = 0; k < KREG; k++) st[k] = work[swz(addrA(tid, k))];
}
__device__ __forceinline__ void rtAC(u64 st[KREG], u64* work, int tid)
{
    __syncthreads();
    #pragma unroll
    for (int k = 0; k < KREG; k++) work[swz(addrA(tid, k))] = st[k];
    __syncthreads();
    #pragma unroll
    for (int k = 0; k < KREG; k++) st[k] = work[swz(addrC(tid, k))];
}
__device__ __forceinline__ void rtCB_ladder(u64 st[KREG], u64* work, int tid)
{
    __syncthreads();
    #pragma unroll
    for (int k = 0; k < KREG; k++) work[swz(addrC(tid, k))] = st[k];
    __syncthreads();
    #pragma unroll
    for (int k = 0; k < KREG; k++) st[k] = work[swz(ladd(addrB(tid, k)))];
}

extern __shared__ u64 smem_u64[];
// [0,4096) work   [4096,8192) enc snapshot   then 180 float2 coeffs

__global__ void __launch_bounds__(NTHR, 3) qtf_main(
    const float* __restrict__ seq,
    const float* __restrict__ W1, const float* __restrict__ b1,
    const float* __restrict__ W2, const float* __restrict__ b2,
    float* __restrict__ out)
{
    u64* work   = smem_u64;
    u64* encs   = smem_u64 + 4096;
    float2* sry = (float2*)(smem_u64 + 8192);
    __shared__ float redbuf[96];      // 8 warps x 12 features
    const int tid = threadIdx.x;
    // heavy-first remap: blocks 0..7 are the t=63 (6-projection) CTAs
    int b_, t_;
    if (blockIdx.x < 8) { b_ = blockIdx.x; t_ = SEQ - 1; }
    else { int ix = blockIdx.x - 8; b_ = ix / 63; t_ = ix % 63; }
    const int bt = b_ * SEQ + t_;
    const int t  = t_;
    const float x = seq[bt];

    for (int j = tid; j < 36;  j += NTHR) sry[j]    = g_ryres[j];
    for (int j = tid; j < 144; j += NTHR) sry[36+j] = g_ryproj[j];

    u64 st[KREG];

    // ======== encode: product state with folded ladder+ring perm (layout A) ========
    {
        float2 F = make_float2(1.0f, 0.0f);
        float2 wv[6][2];
        #pragma unroll
        for (int i = 0; i < NQ; i++) {
            float th = x * (float)(PI_D * (double)(i + 1) / 12.0);
            float ph = x * (float)(PI_D / (double)(i + 1));
            float s, c, sh, ch;
            __sincosf(0.5f*th, &s, &c);
            __sincosf(0.5f*ph, &sh, &ch);
            float am = (c - s) * 0.70710678118654752f;
            float ap = (c + s) * 0.70710678118654752f;
            float2 v0 = make_float2(am*ch, -am*sh);
            float2 v1 = make_float2(ap*ch,  ap*sh);
            if (i >= 2 && i <= 7) {
                int bit = ((tid >> (i-1)) ^ (tid >> i)) & 1;
                F = cmul(F, bit ? v1 : v0);
            } else {
                int vi = (i < 2) ? i : (i - 6);
                wv[vi][0] = v0; wv[vi][1] = v1;
            }
        }
        int a0 = tid & 1, a1 = (tid >> 1) & 1, a7 = (tid >> 7) & 1;
        #pragma unroll
        for (int k = 0; k < KREG; k++) {
            int k0 = k & 1, k1 = (k >> 1) & 1, k2 = (k >> 2) & 1, k3 = (k >> 3) & 1;
            float2 a = cmul(F, (a0 ^ k3)      ? wv[0][1] : wv[0][0]);
            a = cmul(a, (a0 ^ a1 ^ k3) ? wv[1][1] : wv[1][0]);
            a = cmul(a, (a7 ^ k0)      ? wv[2][1] : wv[2][0]);
            a = cmul(a, (k0 ^ k1)      ? wv[3][1] : wv[3][0]);
            a = cmul(a, (k1 ^ k2)      ? wv[4][1] : wv[4][0]);
            a = cmul(a, (k2 ^ k3)      ? wv[5][1] : wv[5][0]);
            st[k] = pk2(a.x, a.y);
        }
    }
    __syncthreads();

    // ======== reservoir (unchanged structure; A/B layouts) ========
    diagA(st, g_diag + 0*128, tid);
    #pragma unroll
    for (int i = 0; i < 5; i++) ry_lane(st, tid, i, sry[i]);
    ry_local(st, 1, sry[8]);  ry_local(st, 2, sry[9]);
    ry_local(st, 4, sry[10]); ry_local(st, 8, sry[11]);
    rtAB(st, work, tid);
    ry_local(st, 1, sry[5]);  ry_local(st, 2, sry[6]); ry_local(st, 4, sry[7]);
    diagB(st, g_diag + 1*128, tid);
    cx011(st, tid);

    diagB(st, g_diag + 2*128, tid);
    #pragma unroll
    for (int i = 0; i < 5; i++) ry_lane(st, tid, i, sry[12+i]);
    ry_local(st, 1, sry[12+5]); ry_local(st, 2, sry[12+6]);
    ry_local(st, 4, sry[12+7]); ry_local(st, 8, sry[12+11]);
    rtBA(st, work, tid);
    ry_local(st, 1, sry[12+8]); ry_local(st, 2, sry[12+9]); ry_local(st, 4, sry[12+10]);
    diagA(st, g_diag + 3*128, tid);
    if (((tid >> 5) & (tid >> 6)) & 1) {   // CZ(0x2AA) straddle pair (q5,q6)
        #pragma unroll
        for (int k = 0; k < KREG; k++) st[k] ^= NEGM;
    }
    cx011(st, tid);

    diagA(st, g_diag + 4*128, tid);
    #pragma unroll
    for (int i = 0; i < 5; i++) ry_lane(st, tid, i, sry[24+i]);
    ry_local(st, 1, sry[24+8]);  ry_local(st, 2, sry[24+9]);
    ry_local(st, 4, sry[24+10]); ry_local(st, 8, sry[24+11]);
    rtAB(st, work, tid);
    ry_local(st, 1, sry[24+5]);  ry_local(st, 2, sry[24+6]); ry_local(st, 4, sry[24+7]);
    diagB(st, g_diag + 5*128, tid);
    cx011(st, tid);

    // snapshot encoded state (layout B; own cells only, plain addressing)
    #pragma unroll
    for (int k = 0; k < KREG; k++) encs[(k<<8) | tid] = st[k];

    // ======== projections (B -> A -> C cycle; Q only at t = SEQ-1) ========
    const bool lastt = (t == SEQ - 1);
    bool first = true;
    for (int h = 0; h < 2; h++) {
        for (int p = 0; p < 3; p++) {
            if (p == 0 && !lastt) continue;
            if (!first) {
                #pragma unroll
                for (int k = 0; k < KREG; k++) st[k] = encs[(k<<8) | tid];
            }
            first = false;
            const int hp = h*3 + p;
            const float2* gp = sry + 36 + hp*24;
            // ---- attn layer 0 ----
            ry_local(st, 1, gp[5]); ry_local(st, 2, gp[6]);
            ry_local(st, 4, gp[7]); ry_local(st, 8, gp[11]);
            ry_lane(st, tid, 4, gp[4]);          // q4 (lane bit 4 in B)
            rtBA(st, work, tid);
            ry_local(st, 1, gp[8]); ry_local(st, 2, gp[9]); ry_local(st, 4, gp[10]);
            rtAC(st, work, tid);
            ry_local(st, 1, gp[0]); ry_local(st, 2, gp[1]);
            ry_local(st, 4, gp[2]); ry_local(st, 8, gp[3]);
            diagC(st, g_diag + (6 + hp)*128, tid);
            rtCB_ladder(st, work, tid);          // ladder folded into gather
            // ---- attn layer 1 (final ladder folded into feature signs) ----
            ry_local(st, 1, gp[12+5]); ry_local(st, 2, gp[12+6]);
            ry_local(st, 4, gp[12+7]); ry_local(st, 8, gp[12+11]);
            ry_lane(st, tid, 4, gp[12+4]);
            rtBA(st, work, tid);
            ry_local(st, 1, gp[12+8]); ry_local(st, 2, gp[12+9]); ry_local(st, 4, gp[12+10]);
            rtAC(st, work, tid);
            ry_local(st, 1, gp[12+0]); ry_local(st, 2, gp[12+1]);
            ry_local(st, 4, gp[12+2]); ry_local(st, 8, gp[12+3]);

            // ---- features in layout C ----
            float P4 = 0.f, P3 = 0.f, P2 = 0.f, P1 = 0.f;
            #pragma unroll
            for (int k = 0; k < KREG; k++) {
                float2 v = up2(st[k]);
                float pr = fmaf(v.x, v.x, v.y*v.y);
                P4 += (__popc(k)     & 1) ? -pr : pr;
                P3 += (__popc(k & 7) & 1) ? -pr : pr;
                P2 += ((k ^ (k>>1))  & 1) ? -pr : pr;
                P1 += ( k            & 1) ? -pr : pr;
            }
            const int fmask[9] = {0xFF, 0xEF, 0x6F, 0x2F, 0x0F, 0x07, 0x03, 0x01, 0x00};
            float acc[NQ];
            #pragma unroll
            for (int q = 0; q < 9; q++)
                acc[q] = (__popc(tid & fmask[q]) & 1) ? -P4 : P4;
            acc[9]  = P3;
            acc[10] = P2;
            acc[11] = P1;
            #pragma unroll
            for (int q = 0; q < NQ; q++) {
                float v = acc[q];
                #pragma unroll
                for (int o = 16; o; o >>= 1)
                    v += __shfl_xor_sync(0xffffffffu, v, o);
                acc[q] = v;
            }
            if ((tid & 31) == 0) {
                int w = tid >> 5;
                #pragma unroll
                for (int q = 0; q < NQ; q++) redbuf[w*NQ + q] = acc[q];
            }
            __syncthreads();
            if (tid < NQ) {
                float s = 0.f;
                #pragma unroll
                for (int w = 0; w < 8; w++) s += redbuf[w*NQ + tid];
                g_qkv[(hp*BT + bt)*NQ + tid] = s;
            }
        }
    }

    // ======== last CTA runs attention + MLP inline ========
    __shared__ int s_last;
    __syncthreads();                 // g_qkv writes done before publish
    __threadfence();
    if (tid == 0) s_last = (atomicAdd(&g_done, 1) == BT - 1) ? 1 : 0;
    __syncthreads();
    if (!s_last) return;
    if (tid == 0) g_done = 0;        // reset for next graph replay
    __threadfence();

    float* feat = (float*)work;      // 8 b * 24
    float* hdn  = feat + 192;        // 8 b * 48
    const int w = tid >> 5, l = tid & 31;
    for (int task = w; task < 16; task += 8) {
        int b = task >> 1, h = task & 1;
        const float* Q = &g_qkv[((h*3 + 0)*BT + b*SEQ + (SEQ-1))*NQ];
        const float* K = &g_qkv[((h*3 + 1)*BT + b*SEQ)*NQ];
        const float* V = &g_qkv[((h*3 + 2)*BT + b*SEQ)*NQ];
        float sc0 = 0.f, sc1 = 0.f;
        #pragma unroll
        for (int q = 0; q < NQ; q++) {
            float qv = Q[q];
            sc0 = fmaf(qv, K[l*NQ + q],      sc0);
            sc1 = fmaf(qv, K[(l+32)*NQ + q], sc1);
        }
        sc0 *= 0.28867513459481287f;
        sc1 *= 0.28867513459481287f;
        float m = fmaxf(sc0, sc1);
        #pragma unroll
        for (int o = 16; o; o >>= 1)
            m = fmaxf(m, __shfl_xor_sync(0xffffffffu, m, o));
        float e0 = expf(sc0 - m), e1 = expf(sc1 - m);
        float sum = e0 + e1;
        #pragma unroll
        for (int o = 16; o; o >>= 1)
            sum += __shfl_xor_sync(0xffffffffu, sum, o);
        float inv = 1.0f / sum;
        float w0 = e0 * inv, w1 = e1 * inv;
        #pragma unroll
        for (int d = 0; d < NQ; d++) {
            float v = fmaf(w0, V[l*NQ + d], w1 * V[(l+32)*NQ + d]);
            #pragma unroll
            for (int o = 16; o; o >>= 1)
                v += __shfl_xor_sync(0xffffffffu, v, o);
            if (l == 0) feat[b*24 + h*NQ + d] = v;
        }
    }
    __syncthreads();
    for (int idx = tid; idx < 384; idx += NTHR) {
        int b = idx / 48, j = idx % 48;
        float a = b1[j];
        #pragma unroll
        for (int i = 0; i < 24; i++) a = fmaf(feat[b*24 + i], W1[i*48 + j], a);
        hdn[b*48 + j] = 0.5f * a * (1.0f + erff(a * 0.7071067811865476f));
    }
    __syncthreads();
    if (tid < 32) {
        int b = tid >> 2, o = tid & 3;
        float a = b2[o];
        #pragma unroll
        for (int j = 0; j < 48; j++) a = fmaf(hdn[b*48 + j], W2[j*4 + o], a);
        out[b*4 + o] = a;
    }
}

extern "C" void kernel_launch(void* const* d_in, const int* in_sizes, int n_in,
                              void* d_out, int out_size)
{
    const float* seq   = (const float*)d_in[0];
    const float* resp  = (const float*)d_in[1];
    const float* headp = (const float*)d_in[2];
    const float* W1    = (const float*)d_in[3];
    const float* b1    = (const float*)d_in[4];
    const float* W2    = (const float*)d_in[5];
    const float* b2    = (const float*)d_in[6];
    float* out = (float*)d_out;

    size_t shbytes = 8192ull*sizeof(u64) + 180ull*sizeof(float2);   // 66,976 B -> occ 3
    cudaFuncSetAttribute(qtf_main, cudaFuncAttributeMaxDynamicSharedMemorySize, (int)shbytes);

    qtf_setup<<<8, 256>>>(resp, headp);
    qtf_main<<<BT, NTHR, shbytes>>>(seq, W1, b1, W2, b2, out);
}

// round 17
// speedup vs baseline: 1.1974x; 1.1645x over previous
#include <cuda_runtime.h>
#include <math.h>

#define NQ    12
#define DIM   4096
#define BATCH 8
#define SEQ   64
#define BT    (BATCH*SEQ)
#define NTHR  256
#define KREG  16
#define NP2   2064            // phase-2 grid: 512*4 KV + 16 Q

#define PI_D 3.14159265358979323846

typedef unsigned long long u64;

// QKV features [head*3+proj][bt][12]
__device__ float  g_qkv[6*BT*NQ];
__device__ float2 g_ryres[36];        // reservoir RY coeffs (cos(t/2), sin(t/2))
__device__ float2 g_ryproj[144];      // projection RY coeffs
__device__ float2 g_diag[12*128];     // diag tables: pass*128 + (lo:0-63 | hi:64-127)
__device__ int    g_done;             // completion counter (reset by last CTA)
__device__ u64    g_encs[(size_t)BT * DIM];   // enc snapshots (layout B)

// ---------------- packed f32x2 helpers ----------------
__device__ __forceinline__ u64 pk2(float lo, float hi) {
    u64 r; asm("mov.b64 %0,{%1,%2};" : "=l"(r) : "f"(lo), "f"(hi)); return r;
}
__device__ __forceinline__ float2 up2(u64 v) {
    float2 r; asm("mov.b64 {%0,%1},%2;" : "=f"(r.x), "=f"(r.y) : "l"(v)); return r;
}
__device__ __forceinline__ u64 mul2_(u64 a, u64 b) {
    u64 d; asm("mul.rn.f32x2 %0,%1,%2;" : "=l"(d) : "l"(a), "l"(b)); return d;
}
__device__ __forceinline__ u64 fma2_(u64 a, u64 b, u64 c) {
    u64 d; asm("fma.rn.f32x2 %0,%1,%2,%3;" : "=l"(d) : "l"(a), "l"(b), "l"(c)); return d;
}
#define NEGM 0x8000000080000000ULL

// ---------------- complex helpers ----------------
__device__ __forceinline__ float2 cmul(float2 a, float2 b) {
    return make_float2(a.x*b.x - a.y*b.y, a.x*b.y + a.y*b.x);
}

// ---------------- setup: RY coeffs + diag tables (CZ folded in) ----------------
__global__ void qtf_setup(const float* __restrict__ resp, const float* __restrict__ headp)
{
    int j = blockIdx.x * blockDim.x + threadIdx.x;
    if (j < 36) {
        float t = resp[j*3];
        g_ryres[j] = make_float2(cosf(0.5f*t), sinf(0.5f*t));
    } else if (j < 180) {
        int s = j - 36, hp = s / 24, gi = s % 24;
        float t = headp[hp*48 + gi*2];
        g_ryproj[s] = make_float2(cosf(0.5f*t), sinf(0.5f*t));
    }
    int e = j - 192;
    if (e >= 0 && e < 12*128) {
        int pass = e >> 7, m = e & 127;
        int is_hi = (m >> 6) & 1, mb = m & 63;
        float ph = 0.f;
        for (int i = 0; i < 6; i++) {
            if ((mb >> i) & 1) {
                int q = i + is_hi*6;
                float f;
                if (pass < 6) {
                    int l = pass >> 1, kind = pass & 1;
                    f = resp[(l*12 + q)*3 + (kind ? 1 : 2)];
                } else {
                    f = headp[(pass - 6)*48 + q*2 + 1];
                }
                ph += f;
            }
        }
        float2 v = make_float2(cosf(ph), sinf(ph));
        int neg = 0;
        if (pass == 1 || pass == 5)       // CZ 0x555 in-half pairs
            neg = __popc(mb & (mb >> 1) & 0x15) & 1;
        else if (pass == 3)               // CZ 0x2AA in-half pairs
            neg = __popc(mb & (mb >> 1) & 0x0A) & 1;
        if (neg) { v.x = -v.x; v.y = -v.y; }
        g_diag[pass*128 + m] = v;
    }
}

// ---------------- layouts ----------------
__device__ __forceinline__ int addrA(int tid, int k) { return (k<<8) | tid; }
__device__ __forceinline__ int addrB(int tid, int k) {
    return (tid & 31) | ((k & 7) << 5) | ((tid >> 5) << 8) | ((k >> 3) << 11);
}
__device__ __forceinline__ int ladd(int d) {
    return ((d ^ (d << 1)) & 0xFFE) | (d & 1);
}

// ---------------- packed RY gate primitives ----------------
__device__ __forceinline__ void ry_lane(u64 st[KREG], int tid, int i, float2 cs)
{
    unsigned lm = 1u << i;
    float s = ((tid >> i) & 1) ? cs.y : -cs.y;
    u64 c2 = pk2(cs.x, cs.x), s2 = pk2(s, s);
    #pragma unroll
    for (int k = 0; k < KREG; k++) {
        float2 v = up2(st[k]);
        float ox = __shfl_xor_sync(0xffffffffu, v.x, lm);
        float oy = __shfl_xor_sync(0xffffffffu, v.y, lm);
        st[k] = fma2_(c2, st[k], mul2_(s2, pk2(ox, oy)));
    }
}
__device__ __forceinline__ void ry_local(u64 st[KREG], int m, float2 cs)
{
    u64 c2 = pk2(cs.x, cs.x), s2 = pk2(cs.y, cs.y), ns2 = pk2(-cs.y, -cs.y);
    #pragma unroll
    for (int k = 0; k < KREG; k++) {
        if (k & m) continue;
        int kk = k | m;
        u64 a = st[k], b = st[kk];
        st[k]  = fma2_(c2, a, mul2_(ns2, b));
        st[kk] = fma2_(s2, a, mul2_(c2, b));
    }
}

// ---------------- diagonal passes ----------------
__device__ __forceinline__ void diagA(u64 st[KREG], const float2* T, int tid)
{
    float2 L = __ldg(&T[tid & 63]);
    int tt = tid >> 6;
    #pragma unroll
    for (int k = 0; k < KREG; k++) {
        float2 u = cmul(L, __ldg(&T[64 + ((k<<2) | tt)]));
        float2 v = up2(st[k]);
        st[k] = pk2(v.x*u.x - v.y*u.y, v.x*u.y + v.y*u.x);
    }
}
__device__ __forceinline__ void diagB(u64 st[KREG], const float2* T, int tid)
{
    int lo0 = tid & 31, t57 = tid >> 5;
    #pragma unroll
    for (int k = 0; k < KREG; k++) {
        float2 L = __ldg(&T[lo0 | ((k & 1) << 5)]);
        float2 H = __ldg(&T[64 + (((k>>1) & 3) | (t57 << 2) | ((k>>3) << 5))]);
        float2 u = cmul(L, H);
        float2 v = up2(st[k]);
        st[k] = pk2(v.x*u.x - v.y*u.y, v.x*u.y + v.y*u.x);
    }
}

__device__ __forceinline__ void cx011(u64 st[KREG], int tid)
{
    if (tid & 1) {
        #pragma unroll
        for (int k = 0; k < 8; k++) {
            u64 t = st[k]; st[k] = st[k+8]; st[k+8] = t;
        }
    }
}

// ---------------- layout roundtrips ----------------
__device__ __forceinline__ void rtAB(u64 st[KREG], u64* work, int tid, bool ladder)
{
    __syncthreads();
    #pragma unroll
    for (int k = 0; k < KREG; k++) work[addrA(tid, k)] = st[k];
    __syncthreads();
    #pragma unroll
    for (int k = 0; k < KREG; k++) {
        int D = addrB(tid, k);
        st[k] = work[ladder ? ladd(D) : D];
    }
}
__device__ __forceinline__ void rtBA(u64 st[KREG], u64* work, int tid)
{
    __syncthreads();
    #pragma unroll
    for (int k = 0; k < KREG; k++) work[addrB(tid, k)] = st[k];
    __syncthreads();
    #pragma unroll
    for (int k = 0; k < KREG; k++) st[k] = work[addrA(tid, k)];
}

extern __shared__ u64 smem_u64[];

// =================== PHASE 1: encode + reservoir -> g_encs ===================
__global__ void __launch_bounds__(NTHR, 3) qtf_phase1(const float* __restrict__ seq)
{
    u64* work   = smem_u64;
    float2* sry = (float2*)(smem_u64 + 4096);   // 36 reservoir coeffs
    const int tid = threadIdx.x;
    const int bt  = blockIdx.x;
    const float x = seq[bt];

    for (int j = tid; j < 36; j += NTHR) sry[j] = g_ryres[j];

    u64 st[KREG];

    // encode: product state with folded ladder+ring perm (layout A)
    {
        float2 F = make_float2(1.0f, 0.0f);
        float2 wv[6][2];
        #pragma unroll
        for (int i = 0; i < NQ; i++) {
            float th = x * (float)(PI_D * (double)(i + 1) / 12.0);
            float ph = x * (float)(PI_D / (double)(i + 1));
            float s, c, sh, ch;
            __sincosf(0.5f*th, &s, &c);
            __sincosf(0.5f*ph, &sh, &ch);
            float am = (c - s) * 0.70710678118654752f;
            float ap = (c + s) * 0.70710678118654752f;
            float2 v0 = make_float2(am*ch, -am*sh);
            float2 v1 = make_float2(ap*ch,  ap*sh);
            if (i >= 2 && i <= 7) {
                int bit = ((tid >> (i-1)) ^ (tid >> i)) & 1;
                F = cmul(F, bit ? v1 : v0);
            } else {
                int vi = (i < 2) ? i : (i - 6);
                wv[vi][0] = v0; wv[vi][1] = v1;
            }
        }
        int a0 = tid & 1, a1 = (tid >> 1) & 1, a7 = (tid >> 7) & 1;
        #pragma unroll
        for (int k = 0; k < KREG; k++) {
            int k0 = k & 1, k1 = (k >> 1) & 1, k2 = (k >> 2) & 1, k3 = (k >> 3) & 1;
            float2 a = cmul(F, (a0 ^ k3)      ? wv[0][1] : wv[0][0]);
            a = cmul(a, (a0 ^ a1 ^ k3) ? wv[1][1] : wv[1][0]);
            a = cmul(a, (a7 ^ k0)      ? wv[2][1] : wv[2][0]);
            a = cmul(a, (k0 ^ k1)      ? wv[3][1] : wv[3][0]);
            a = cmul(a, (k1 ^ k2)      ? wv[4][1] : wv[4][0]);
            a = cmul(a, (k2 ^ k3)      ? wv[5][1] : wv[5][0]);
            st[k] = pk2(a.x, a.y);
        }
    }
    __syncthreads();

    // reservoir (A/B alternation)
    diagA(st, g_diag + 0*128, tid);
    #pragma unroll
    for (int i = 0; i < 5; i++) ry_lane(st, tid, i, sry[i]);
    ry_local(st, 1, sry[8]);  ry_local(st, 2, sry[9]);
    ry_local(st, 4, sry[10]); ry_local(st, 8, sry[11]);
    rtAB(st, work, tid, false);
    ry_local(st, 1, sry[5]);  ry_local(st, 2, sry[6]); ry_local(st, 4, sry[7]);
    diagB(st, g_diag + 1*128, tid);
    cx011(st, tid);

    diagB(st, g_diag + 2*128, tid);
    #pragma unroll
    for (int i = 0; i < 5; i++) ry_lane(st, tid, i, sry[12+i]);
    ry_local(st, 1, sry[12+5]); ry_local(st, 2, sry[12+6]);
    ry_local(st, 4, sry[12+7]); ry_local(st, 8, sry[12+11]);
    rtBA(st, work, tid);
    ry_local(st, 1, sry[12+8]); ry_local(st, 2, sry[12+9]); ry_local(st, 4, sry[12+10]);
    diagA(st, g_diag + 3*128, tid);
    if (((tid >> 5) & (tid >> 6)) & 1) {
        #pragma unroll
        for (int k = 0; k < KREG; k++) st[k] ^= NEGM;
    }
    cx011(st, tid);

    diagA(st, g_diag + 4*128, tid);
    #pragma unroll
    for (int i = 0; i < 5; i++) ry_lane(st, tid, i, sry[24+i]);
    ry_local(st, 1, sry[24+8]);  ry_local(st, 2, sry[24+9]);
    ry_local(st, 4, sry[24+10]); ry_local(st, 8, sry[24+11]);
    rtAB(st, work, tid, false);
    ry_local(st, 1, sry[24+5]);  ry_local(st, 2, sry[24+6]); ry_local(st, 4, sry[24+7]);
    diagB(st, g_diag + 5*128, tid);
    cx011(st, tid);

    // store enc snapshot (layout B)
    u64* encg = g_encs + ((size_t)bt << 12);
    #pragma unroll
    for (int k = 0; k < KREG; k++) encg[(k<<8) | tid] = st[k];
}

// =================== PHASE 2: one projection per CTA (+fused head) ===================
__global__ void __launch_bounds__(NTHR, 4) qtf_phase2(
    const float* __restrict__ W1, const float* __restrict__ b1,
    const float* __restrict__ W2, const float* __restrict__ b2,
    float* __restrict__ out)
{
    u64* work   = smem_u64;
    float2* sgp = (float2*)(smem_u64 + 4096);   // 24 coeffs for this projection
    __shared__ float redbuf[96];
    const int tid = threadIdx.x;

    int bt, h, p;
    if (blockIdx.x < 16) {              // Q projections of the 8 last-t states
        int b = blockIdx.x >> 1;
        h = blockIdx.x & 1; p = 0;
        bt = b * SEQ + (SEQ - 1);
    } else {
        int ix = blockIdx.x - 16;
        bt = ix >> 2;
        int j = ix & 3;
        h = j >> 1; p = 1 + (j & 1);
    }
    const int hp = h*3 + p;

    if (tid < 24) sgp[tid] = g_ryproj[hp*24 + tid];
    __syncthreads();

    // load enc snapshot (layout B)
    const u64* encg = g_encs + ((size_t)bt << 12);
    u64 st[KREG];
    #pragma unroll
    for (int k = 0; k < KREG; k++) st[k] = __ldg(&encg[(k<<8) | tid]);

    const float2* gp = sgp;
    // attn layer 0 (state in B)
    #pragma unroll
    for (int i = 0; i < 5; i++) ry_lane(st, tid, i, gp[i]);
    ry_local(st, 1, gp[5]); ry_local(st, 2, gp[6]);
    ry_local(st, 4, gp[7]); ry_local(st, 8, gp[11]);
    rtBA(st, work, tid);
    ry_local(st, 1, gp[8]); ry_local(st, 2, gp[9]); ry_local(st, 4, gp[10]);
    diagA(st, g_diag + (6 + hp)*128, tid);
    rtAB(st, work, tid, true);          // ladder folded into gather
    // attn layer 1 (final RZ dropped: |amp|^2)
    #pragma unroll
    for (int i = 0; i < 5; i++) ry_lane(st, tid, i, gp[12+i]);
    ry_local(st, 1, gp[12+5]); ry_local(st, 2, gp[12+6]);
    ry_local(st, 4, gp[12+7]); ry_local(st, 8, gp[12+11]);
    rtBA(st, work, tid);
    ry_local(st, 1, gp[12+8]); ry_local(st, 2, gp[12+9]); ry_local(st, 4, gp[12+10]);

    // features (layout A, final ladder folded into sign masks)
    float S = 0.f, B0 = 0.f, B1 = 0.f, B2 = 0.f, B3 = 0.f;
    #pragma unroll
    for (int k = 0; k < KREG; k++) {
        float2 v = up2(st[k]);
        float pr = fmaf(v.x, v.x, v.y*v.y);
        S += pr;
        B0 += ( k          & 1) ? -pr : pr;
        B1 += ((k ^ (k>>1))& 1) ? -pr : pr;
        B2 += (__popc(k & 7)  & 1) ? -pr : pr;
        B3 += (__popc(k & 15) & 1) ? -pr : pr;
    }
    float tsgn = (__popc(tid) & 1) ? -1.f : 1.f;
    float acc[NQ];
    acc[0] = tsgn * B3;
    acc[1] = tsgn * B2;
    acc[2] = tsgn * B1;
    acc[3] = tsgn * B0;
    #pragma unroll
    for (int q = 4; q < NQ; q++) {
        int mt = 0xFF >> (q - 4);
        acc[q] = (__popc(tid & mt) & 1) ? -S : S;
    }
    #pragma unroll
    for (int q = 0; q < NQ; q++) {
        float v = acc[q];
        #pragma unroll
        for (int o = 16; o; o >>= 1)
            v += __shfl_xor_sync(0xffffffffu, v, o);
        acc[q] = v;
    }
    if ((tid & 31) == 0) {
        int w = tid >> 5;
        #pragma unroll
        for (int q = 0; q < NQ; q++) redbuf[w*NQ + q] = acc[q];
    }
    __syncthreads();
    if (tid < NQ) {
        float s = 0.f;
        #pragma unroll
        for (int w = 0; w < 8; w++) s += redbuf[w*NQ + tid];
        g_qkv[(hp*BT + bt)*NQ + tid] = s;
    }

    // ---- last CTA runs attention + MLP inline ----
    __shared__ int s_last;
    __syncthreads();
    __threadfence();
    if (tid == 0) s_last = (atomicAdd(&g_done, 1) == NP2 - 1) ? 1 : 0;
    __syncthreads();
    if (!s_last) return;
    if (tid == 0) g_done = 0;        // reset for next graph replay
    __threadfence();

    float* feat = (float*)work;      // 8 b * 24
    float* hdn  = feat + 192;        // 8 b * 48
    const int w = tid >> 5, l = tid & 31;
    for (int task = w; task < 16; task += 8) {
        int b = task >> 1, hh = task & 1;
        const float* Q = &g_qkv[((hh*3 + 0)*BT + b*SEQ + (SEQ-1))*NQ];
        const float* K = &g_qkv[((hh*3 + 1)*BT + b*SEQ)*NQ];
        const float* V = &g_qkv[((hh*3 + 2)*BT + b*SEQ)*NQ];
        float sc0 = 0.f, sc1 = 0.f;
        #pragma unroll
        for (int q = 0; q < NQ; q++) {
            float qv = Q[q];
            sc0 = fmaf(qv, K[l*NQ + q],      sc0);
            sc1 = fmaf(qv, K[(l+32)*NQ + q], sc1);
        }
        sc0 *= 0.28867513459481287f;
        sc1 *= 0.28867513459481287f;
        float m = fmaxf(sc0, sc1);
        #pragma unroll
        for (int o = 16; o; o >>= 1)
            m = fmaxf(m, __shfl_xor_sync(0xffffffffu, m, o));
        float e0 = expf(sc0 - m), e1 = expf(sc1 - m);
        float sum = e0 + e1;
        #pragma unroll
        for (int o = 16; o; o >>= 1)
            sum += __shfl_xor_sync(0xffffffffu, sum, o);
        float inv = 1.0f / sum;
        float w0 = e0 * inv, w1 = e1 * inv;
        #pragma unroll
        for (int d = 0; d < NQ; d++) {
            float v = fmaf(w0, V[l*NQ + d], w1 * V[(l+32)*NQ + d]);
            #pragma unroll
            for (int o = 16; o; o >>= 1)
                v += __shfl_xor_sync(0xffffffffu, v, o);
            if (l == 0) feat[b*24 + hh*NQ + d] = v;
        }
    }
    __syncthreads();
    for (int idx = tid; idx < 384; idx += NTHR) {
        int b = idx / 48, j = idx % 48;
        float a = b1[j];
        #pragma unroll
        for (int i = 0; i < 24; i++) a = fmaf(feat[b*24 + i], W1[i*48 + j], a);
        hdn[b*48 + j] = 0.5f * a * (1.0f + erff(a * 0.7071067811865476f));
    }
    __syncthreads();
    if (tid < 32) {
        int b = tid >> 2, o = tid & 3;
        float a = b2[o];
        #pragma unroll
        for (int j = 0; j < 48; j++) a = fmaf(hdn[b*48 + j], W2[j*4 + o], a);
        out[b*4 + o] = a;
    }
}

extern "C" void kernel_launch(void* const* d_in, const int* in_sizes, int n_in,
                              void* d_out, int out_size)
{
    const float* seq   = (const float*)d_in[0];
    const float* resp  = (const float*)d_in[1];
    const float* headp = (const float*)d_in[2];
    const float* W1    = (const float*)d_in[3];
    const float* b1    = (const float*)d_in[4];
    const float* W2    = (const float*)d_in[5];
    const float* b2    = (const float*)d_in[6];
    float* out = (float*)d_out;

    size_t sh1 = 4096ull*sizeof(u64) + 36ull*sizeof(float2);    // 33,056 B
    size_t sh2 = 4096ull*sizeof(u64) + 24ull*sizeof(float2);    // 32,960 B
    cudaFuncSetAttribute(qtf_phase1, cudaFuncAttributeMaxDynamicSharedMemorySize, (int)sh1);
    cudaFuncSetAttribute(qtf_phase2, cudaFuncAttributeMaxDynamicSharedMemorySize, (int)sh2);

    qtf_setup<<<8, 256>>>(resp, headp);
    qtf_phase1<<<BT, NTHR, sh1>>>(seq);
    qtf_phase2<<<NP2, NTHR, sh2>>>(W1, b1, W2, b2, out);
}